// round 7
// baseline (speedup 1.0000x reference)
#include <cuda_runtime.h>
#include <cstdint>

// SpatialConv implicit GEMM, tf32 mma.sync fed RAW fp32 bits (HW truncates
// to tf32) — no cvt anywhere. cp.async double-buffered staging.
// CTA: 128 Co x 64 px (1 row), 256 thr, 8 warps (4m x 2n), warp 32x32.
// K-step kb = tap kb over 8 channels (lane channels tig, tig+4).
// taps: 0:(0,0) 1:(-1,0) 2:(0,-1) 3:(0,1) 4:(1,0)

#define CI 256
#define CO 256
#define HH 64
#define WW 64
#define NB 16
#define KTOT 1280
#define BM 128
#define NTH 256
#define CCH 8            // channels per chunk
#define CK 40            // K per chunk (5 k8-steps)
#define NCHK 32
#define AST 44           // A stride: 12*gid+5*tig all-distinct mod 32
#define CST 216          // X channel stride (3 rows x 72): 24*tig+gid distinct
#define AFL (BM * AST)   // 5632 floats
#define XFL (CCH * CST)  // 1728 floats
#define DYN ((2 * AFL + 2 * XFL) * 4)   // 58880 B

__device__ __forceinline__ void cpa16(uint32_t dst, const void* src, int srcsz) {
    asm volatile("cp.async.cg.shared.global [%0], [%1], 16, %2;"
                 :: "r"(dst), "l"(src), "r"(srcsz));
}

__global__ __launch_bounds__(NTH, 3)
void conv_mma_kernel(const float* __restrict__ x,
                     const float* __restrict__ wt,
                     float* __restrict__ out)
{
    extern __shared__ uint32_t sm[];
    const int tid  = threadIdx.x;
    const int lane = tid & 31, wid = tid >> 5;
    const int wm   = wid >> 1;    // 0..3: 32-co tile
    const int wn   = wid & 1;     // 0..1: 32-px tile
    const int gid  = lane >> 2, tig = lane & 3;
    const int cob  = blockIdx.x * BM;
    const int h    = blockIdx.y;
    const int n    = blockIdx.z;

    uint32_t* A_[2] = {sm, sm + AFL};
    uint32_t* X_[2] = {sm + 2 * AFL, sm + 2 * AFL + XFL};
    const uint32_t smB = (uint32_t)__cvta_generic_to_shared(sm);
    const uint32_t aB[2] = {smB, smB + AFL * 4};
    const uint32_t xB[2] = {smB + 2 * AFL * 4, smB + (2 * AFL + XFL) * 4};

    // zero X border cols (0..3, 68..71), 3 rows, both buffers; never rewritten
    for (int e = tid; e < 2 * CCH * 3 * 8; e += NTH) {
        int b = e / (CCH * 3 * 8), r2 = e % (CCH * 3 * 8);
        int c = r2 / 24, r = (r2 >> 3) % 3, q = r2 & 7;
        X_[b][c * CST + r * 72 + ((q < 4) ? q : (64 + q))] = 0;
    }

    float acc[2][4][4];
#pragma unroll
    for (int mi = 0; mi < 2; mi++)
#pragma unroll
        for (int ni = 0; ni < 4; ni++)
#pragma unroll
            for (int r = 0; r < 4; r++) acc[mi][ni][r] = 0.f;

    auto stage = [&](int chk, int buf) {
        // A: 128 o x 40 k = 1280 x 16B -> 5/thread
#pragma unroll
        for (int i = 0; i < 5; i++) {
            int e = tid + i * NTH;
            int o = e / 10, q = e % 10;
            cpa16(aB[buf] + (uint32_t)((o * AST + q * 4) * 4),
                  wt + (size_t)(cob + o) * KTOT + chk * CK + q * 4, 16);
        }
        // X: 8 ch x 3 rows (h-1..h+1) x 64 px = 384 x 16B
        for (int e = tid; e < CCH * 3 * 16; e += NTH) {
            int c = e / 48, r = (e >> 4) % 3, q = e & 15;
            int gh = h - 1 + r;
            int ok = ((unsigned)gh < HH) ? 16 : 0;
            int ghc = ok ? gh : 0;
            cpa16(xB[buf] + (uint32_t)((c * CST + r * 72 + 4 + q * 4) * 4),
                  x + (((size_t)n * CI + chk * CCH + c) * HH + ghc) * WW + q * 4, ok);
        }
    };

    stage(0, 0);
    asm volatile("cp.async.commit_group;");

    const int ROW[5] = {1, 0, 1, 1, 2};
    const int DX5[5] = {0, 0, -1, 1, 0};

    for (int chk = 0; chk < NCHK; chk++) {
        const int buf = chk & 1;
        if (chk + 1 < NCHK) stage(chk + 1, buf ^ 1);
        asm volatile("cp.async.commit_group;");
        asm volatile("cp.async.wait_group 1;");
        __syncthreads();

        const uint32_t* A = A_[buf];
        const uint32_t* X = X_[buf];

#pragma unroll
        for (int kb = 0; kb < 5; kb++) {
            const int rr = ROW[kb];
            const int dx = DX5[kb];

            uint32_t a[2][4], b[4][2];
#pragma unroll
            for (int mi = 0; mi < 2; mi++) {
                int r  = wm * 32 + mi * 16 + gid;
                int c1 = tig * 5 + kb;
                int c2 = (tig + 4) * 5 + kb;
                a[mi][0] = A[r * AST + c1];
                a[mi][1] = A[(r + 8) * AST + c1];
                a[mi][2] = A[r * AST + c2];
                a[mi][3] = A[(r + 8) * AST + c2];
            }
#pragma unroll
            for (int ni = 0; ni < 4; ni++) {
                int cc = wn * 32 + ni * 8 + gid + 4 + dx;
                b[ni][0] = X[tig * CST + rr * 72 + cc];
                b[ni][1] = X[(tig + 4) * CST + rr * 72 + cc];
            }
#pragma unroll
            for (int mi = 0; mi < 2; mi++)
#pragma unroll
                for (int ni = 0; ni < 4; ni++) {
                    asm volatile(
                        "mma.sync.aligned.m16n8k8.row.col.f32.tf32.tf32.f32 "
                        "{%0,%1,%2,%3}, {%4,%5,%6,%7}, {%8,%9}, {%0,%1,%2,%3};"
                        : "+f"(acc[mi][ni][0]), "+f"(acc[mi][ni][1]),
                          "+f"(acc[mi][ni][2]), "+f"(acc[mi][ni][3])
                        : "r"(a[mi][0]), "r"(a[mi][1]), "r"(a[mi][2]), "r"(a[mi][3]),
                          "r"(b[ni][0]), "r"(b[ni][1]));
                }
        }
        __syncthreads();
    }

    // epilogue
#pragma unroll
    for (int mi = 0; mi < 2; mi++) {
        int co0 = cob + wm * 32 + mi * 16 + gid;
#pragma unroll
        for (int ni = 0; ni < 4; ni++) {
            int c0 = wn * 32 + ni * 8 + tig * 2;
            *(float2*)&out[(((size_t)n * CO + co0) * HH + h) * WW + c0] =
                make_float2(acc[mi][ni][0], acc[mi][ni][1]);
            *(float2*)&out[(((size_t)n * CO + co0 + 8) * HH + h) * WW + c0] =
                make_float2(acc[mi][ni][2], acc[mi][ni][3]);
        }
    }
}

extern "C" void kernel_launch(void* const* d_in, const int* in_sizes, int n_in,
                              void* d_out, int out_size)
{
    const float* x  = (const float*)d_in[0];
    const float* wt = (const float*)d_in[1];
    float* out = (float*)d_out;

    cudaFuncSetAttribute(conv_mma_kernel,
                         cudaFuncAttributeMaxDynamicSharedMemorySize, DYN);
    dim3 grid(CO / BM, HH, NB);   // (2, 64, 16) = 2048 CTAs
    conv_mma_kernel<<<grid, NTH, DYN>>>(x, wt, out);
}

// round 9
// speedup vs baseline: 2.2947x; 2.2947x over previous
#include <cuda_runtime.h>
#include <cuda_fp16.h>
#include <cstdint>

// SpatialConv implicit GEMM, fp16 mma.sync.m16n8k16 (f32 accum).
// Prep kernels pre-pack weights (tap-major half2 channel pairs) and x
// (channel-pair-interleaved half2) so the main loop is pure cp.async + LDS + HMMA.
// CTA: 128 Co x 128 px (2 rows), 256 thr, 8 warps (4m x 2n), warp 32x64.
// taps: 0:(0,0) 1:(-1,0) 2:(0,-1) 3:(0,1) 4:(1,0)

#define CI 256
#define CO 256
#define HH 64
#define WW 64
#define NB 16
#define NTH 256
#define NCHK 16            // 16 channels per chunk
#define A_ROW 136          // u32 stride per (tap,cpair) row: 136%32=8 -> bank-free
#define A_U32 (5*8*A_ROW)  // 5440
#define X_CP 296           // u32 stride per cpair (4 rows x 72 + pad8): 296%32=8
#define X_U32 (8*X_CP)     // 2368
#define DYN ((2*(A_U32+X_U32))*4)   // 62464 B

__device__ __align__(16) uint32_t g_wti[5 * 128 * 256];          // [tap][cp][o]
__device__ __align__(16) uint32_t g_xi[(size_t)NB * 128 * HH * WW]; // [n][cp][h][w]

__global__ void prep_w(const float* __restrict__ wt) {
    int idx = blockIdx.x * blockDim.x + threadIdx.x;
    if (idx >= 5 * 128 * 256) return;
    int o = idx & 255, cp = (idx >> 8) & 127, tap = idx >> 15;
    float a = wt[(size_t)o * 1280 + (2 * cp) * 5 + tap];
    float b = wt[(size_t)o * 1280 + (2 * cp + 1) * 5 + tap];
    __half2 h = __floats2half2_rn(a, b);
    g_wti[idx] = *(uint32_t*)&h;
}
__global__ void prep_x(const float* __restrict__ x) {
    size_t idx = (size_t)blockIdx.x * blockDim.x + threadIdx.x;
    if (idx >= (size_t)NB * 128 * HH * WW) return;
    int w = idx & 63, h = (idx >> 6) & 63;
    int cp = (idx >> 12) & 127, n = (int)(idx >> 19);
    size_t base = (((size_t)n * CI + 2 * cp) * HH + h) * WW + w;
    __half2 v = __floats2half2_rn(x[base], x[base + (size_t)HH * WW]);
    g_xi[idx] = *(uint32_t*)&v;
}

__device__ __forceinline__ void cpa16(uint32_t dst, const void* src, int srcsz) {
    asm volatile("cp.async.cg.shared.global [%0], [%1], 16, %2;"
                 :: "r"(dst), "l"(src), "r"(srcsz));
}

__global__ __launch_bounds__(NTH, 2)
void conv_mma_kernel(float* __restrict__ out)
{
    extern __shared__ uint32_t sm[];
    const int tid  = threadIdx.x;
    const int lane = tid & 31, wid = tid >> 5;
    const int wm   = wid >> 1;      // 0..3 : 32-co tile
    const int wn   = wid & 1;       // 0..1 : output row
    const int gid  = lane >> 2, tig = lane & 3;
    const int cob  = blockIdx.x * 128;
    const int h0   = blockIdx.y * 2;
    const int n    = blockIdx.z;

    uint32_t* A_[2] = {sm, sm + A_U32};
    uint32_t* X_[2] = {sm + 2 * A_U32, sm + 2 * A_U32 + X_U32};
    const uint32_t smB = (uint32_t)__cvta_generic_to_shared(sm);
    const uint32_t aB[2] = {smB, smB + A_U32 * 4};
    const uint32_t xB[2] = {smB + 2 * A_U32 * 4, smB + (2 * A_U32 + X_U32) * 4};

    // zero X border cols (0..3 and 68..71) in all 4 rows, both buffers
    for (int e = tid; e < 2 * 8 * 4 * 8; e += NTH) {
        int b = e >> 8, r2 = e & 255;
        int c = r2 >> 5, r = (r2 >> 3) & 3, q = r2 & 7;
        X_[b][c * X_CP + r * 72 + ((q < 4) ? q : (64 + q))] = 0;
    }

    float acc[2][8][4];
#pragma unroll
    for (int mi = 0; mi < 2; mi++)
#pragma unroll
        for (int ni = 0; ni < 8; ni++)
#pragma unroll
            for (int r = 0; r < 4; r++) acc[mi][ni][r] = 0.f;

    auto stage = [&](int chk, int buf) {
        const int cp0 = chk * 8;
        // A: 5 taps x 8 cpairs x 128 o (u32) = 40 x 512B -> 5 ops/thread
#pragma unroll
        for (int i = 0; i < 5; i++) {
            int e = tid + i * NTH;
            int t = e >> 8, rem = e & 255, p = rem >> 5, q = rem & 31;
            cpa16(aB[buf] + (uint32_t)(((t * 8 + p) * A_ROW + q * 4) * 4),
                  g_wti + ((t * 128 + cp0 + p) * 256 + cob + q * 4), 16);
        }
        // X: 8 cpairs x 4 rows (h0-1..h0+2) x 64 px -> 2 ops/thread
#pragma unroll
        for (int i = 0; i < 2; i++) {
            int e = tid + i * NTH;
            int c = e >> 6, r = (e >> 4) & 3, q = e & 15;
            int gh = h0 - 1 + r;
            int ok = ((unsigned)gh < HH) ? 16 : 0;
            int ghc = ok ? gh : 0;
            cpa16(xB[buf] + (uint32_t)((c * X_CP + r * 72 + 4 + q * 4) * 4),
                  g_xi + (((size_t)(n * 128 + cp0 + c) * HH + ghc) * WW + q * 4), ok);
        }
    };

    stage(0, 0);
    asm volatile("cp.async.commit_group;");

    const int ROW[5] = {1, 0, 1, 1, 2};
    const int DX5[5] = {0, 0, -1, 1, 0};

    for (int chk = 0; chk < NCHK; chk++) {
        const int buf = chk & 1;
        if (chk + 1 < NCHK) stage(chk + 1, buf ^ 1);
        asm volatile("cp.async.commit_group;");
        asm volatile("cp.async.wait_group 1;");
        __syncthreads();

        const uint32_t* A = A_[buf];
        const uint32_t* X = X_[buf];

#pragma unroll
        for (int tap = 0; tap < 5; tap++) {
            const int rr = ROW[tap] + wn;
            const int dx = DX5[tap];

            uint32_t a[2][4], b[8][2];
#pragma unroll
            for (int mi = 0; mi < 2; mi++) {
                int r = wm * 32 + mi * 16 + gid;
                a[mi][0] = A[(tap * 8 + tig) * A_ROW + r];
                a[mi][1] = A[(tap * 8 + tig) * A_ROW + r + 8];
                a[mi][2] = A[(tap * 8 + tig + 4) * A_ROW + r];
                a[mi][3] = A[(tap * 8 + tig + 4) * A_ROW + r + 8];
            }
#pragma unroll
            for (int ni = 0; ni < 8; ni++) {
                int cc = rr * 72 + ni * 8 + gid + 4 + dx;
                b[ni][0] = X[tig * X_CP + cc];
                b[ni][1] = X[(tig + 4) * X_CP + cc];
            }
#pragma unroll
            for (int mi = 0; mi < 2; mi++)
#pragma unroll
                for (int ni = 0; ni < 8; ni++) {
                    asm volatile(
                        "mma.sync.aligned.m16n8k16.row.col.f32.f16.f16.f32 "
                        "{%0,%1,%2,%3}, {%4,%5,%6,%7}, {%8,%9}, {%0,%1,%2,%3};"
                        : "+f"(acc[mi][ni][0]), "+f"(acc[mi][ni][1]),
                          "+f"(acc[mi][ni][2]), "+f"(acc[mi][ni][3])
                        : "r"(a[mi][0]), "r"(a[mi][1]), "r"(a[mi][2]), "r"(a[mi][3]),
                          "r"(b[ni][0]), "r"(b[ni][1]));
                }
        }
        __syncthreads();
    }

    // epilogue: warp wn owns row h0+wn
    const int h = h0 + wn;
#pragma unroll
    for (int mi = 0; mi < 2; mi++) {
        int co0 = cob + wm * 32 + mi * 16 + gid;
#pragma unroll
        for (int ni = 0; ni < 8; ni++) {
            int c0 = ni * 8 + tig * 2;
            *(float2*)&out[(((size_t)n * CO + co0) * HH + h) * WW + c0] =
                make_float2(acc[mi][ni][0], acc[mi][ni][1]);
            *(float2*)&out[(((size_t)n * CO + co0 + 8) * HH + h) * WW + c0] =
                make_float2(acc[mi][ni][2], acc[mi][ni][3]);
        }
    }
}

extern "C" void kernel_launch(void* const* d_in, const int* in_sizes, int n_in,
                              void* d_out, int out_size)
{
    const float* x  = (const float*)d_in[0];
    const float* wt = (const float*)d_in[1];
    float* out = (float*)d_out;

    prep_w<<<(5 * 128 * 256 + 255) / 256, 256>>>(wt);
    size_t nxi = (size_t)NB * 128 * HH * WW;
    prep_x<<<(unsigned)((nxi + 255) / 256), 256>>>(x);

    cudaFuncSetAttribute(conv_mma_kernel,
                         cudaFuncAttributeMaxDynamicSharedMemorySize, DYN);
    dim3 grid(CO / 128, HH / 2, NB);   // (2, 32, 16) = 1024 CTAs
    conv_mma_kernel<<<grid, NTH, DYN>>>(out);
}